// round 12
// baseline (speedup 1.0000x reference)
#include <cuda_runtime.h>
#include <cuda_bf16.h>

// GaussianKernel via bf16 tensor-core GEMM, round 11:
//   out[b,l,o] = exp(-gamma*(|x|^2 + |w|^2 - 2 x.w)) + bias[o]
// GEMM [M=131072, N=64, K=288]. Change vs 59.2us version: depth-2 software
// pipeline. 18 chunks of 16 k-rows through a 3-buffer smem ring, one barrier
// per chunk; LDGs issued at iter i are consumed at iter i+2 (~2 iterations
// ~600cyc lookahead), fully hiding DRAM latency. smem ~44KB, 3 CTAs/SM.

#define K_DIM   288
#define KCHUNK  16
#define NCHUNK  18
#define O_DIM   64
#define L_DIM   16384
#define TPB     256
#define MT      128
#define KSTEPS  18
#define A_PITCH_B 256                      // bytes per A row (128 bf16)
#define A_BUF_B  (KCHUNK * A_PITCH_B)      // 4096 per buffer

#define WF_UINT4 (KSTEPS * 4 * 32)         // 2304 uint4 = 36864 B

__device__ uint4 g_wf[WF_UINT4];           // packed B fragments
__device__ float g_w2[O_DIM];

// smem layout (bytes)
#define SMEM_WF   (3 * A_BUF_B)            // 12288
#define SMEM_W2   (SMEM_WF + WF_UINT4 * 16)
#define SMEM_X2   (SMEM_W2 + O_DIM * 4)
#define SMEM_TOT  (SMEM_X2 + MT * 4)       // 49920 B

// ---------------------------------------------------------------------------
__global__ void gauss_init_kernel(const float* __restrict__ w)
{
    const int e = blockIdx.x * 256 + threadIdx.x;
    if (e < WF_UINT4) {
        const int lane = e & 31, nbp = (e >> 5) & 3, s = e >> 7;
        const int t = lane & 3, g = lane >> 2;
        const int k0 = s * 16 + t * 2;
        const int n0 = (2 * nbp) * 8 + g;
        const int n1 = n0 + 8;
        uint4 r;
        __nv_bfloat162 p;
        p = __float22bfloat162_rn(make_float2(w[(size_t)k0 * O_DIM + n0],
                                              w[(size_t)(k0 + 1) * O_DIM + n0]));
        r.x = *(unsigned*)&p;
        p = __float22bfloat162_rn(make_float2(w[(size_t)(k0 + 8) * O_DIM + n0],
                                              w[(size_t)(k0 + 9) * O_DIM + n0]));
        r.y = *(unsigned*)&p;
        p = __float22bfloat162_rn(make_float2(w[(size_t)k0 * O_DIM + n1],
                                              w[(size_t)(k0 + 1) * O_DIM + n1]));
        r.z = *(unsigned*)&p;
        p = __float22bfloat162_rn(make_float2(w[(size_t)(k0 + 8) * O_DIM + n1],
                                              w[(size_t)(k0 + 9) * O_DIM + n1]));
        r.w = *(unsigned*)&p;
        g_wf[e] = r;
    }
    if (blockIdx.x == 0 && threadIdx.x < O_DIM) {
        float s = 0.f;
        #pragma unroll 8
        for (int k = 0; k < K_DIM; k++) {
            const float v = w[(size_t)k * O_DIM + threadIdx.x];
            s = fmaf(v, v, s);
        }
        g_w2[threadIdx.x] = s;
    }
}

// ---------------------------------------------------------------------------
__global__ void __launch_bounds__(TPB, 3)
gauss_mma_kernel(const float* __restrict__ x,
                 const float* __restrict__ bias,
                 const float* __restrict__ gptr,
                 float* __restrict__ out)
{
    extern __shared__ char smem[];
    char*     Ab  = smem;                            // 3 x [16][256B] ring
    uint4*    wfs = (uint4*)(smem + SMEM_WF);        // [18*4][32]
    float*    w2s = (float*)(smem + SMEM_W2);
    float*    x2s = (float*)(smem + SMEM_X2);

    const int tid  = threadIdx.x;
    const int lane = tid & 31;
    const int wp   = tid >> 5;                       // 0..7

    const int m0 = blockIdx.x * MT;                  // 1024 CTAs
    const int b  = m0 >> 14;
    const int lb = m0 & (L_DIM - 1);
    const float* xb = x + (size_t)b * K_DIM * L_DIM + lb;

    // ---- Copy packed w fragments + w2 to smem ----
    #pragma unroll
    for (int i = 0; i < WF_UINT4 / TPB; i++)         // 9
        wfs[tid + TPB * i] = g_wf[tid + TPB * i];
    if (tid < O_DIM) w2s[tid] = g_w2[tid];

    // Load mapping: lsub = lane&3, ksl = lane>>2; l = (wp*4+lsub)*4 + {0..3};
    // chunk c covers k = c*16 + p*8 + ksl, p = 0..1.
    const int lsub = lane & 3;
    const int ksl  = lane >> 2;                      // k&7
    const int l0t  = (wp * 4 + lsub) * 4;
    const float* xp = xb + l0t + (size_t)ksl * L_DIM;
    char* ap = Ab + ((l0t * 2) ^ (ksl * 16)) + (size_t)ksl * A_PITCH_B;

    // ldmatrix source address within buffer 0
    unsigned aAddr;
    {
        const int kr = (lane & 7) | ((lane >> 4) << 3);
        const int cb = 2 * wp + ((lane >> 3) & 1);
        const char* p = Ab + (size_t)kr * A_PITCH_B + ((cb ^ (lane & 7)) * 16);
        aAddr = (unsigned)__cvta_generic_to_shared(p);
    }

    const int g = lane >> 2;
    const int t = lane & 3;
    const int row = wp * 16 + g;

    float c[8][4];
    #pragma unroll
    for (int nb = 0; nb < 8; nb++)
        #pragma unroll
        for (int q = 0; q < 4; q++) c[nb][q] = 0.f;

    float s0 = 0.f, s1 = 0.f, s2 = 0.f, s3 = 0.f;    // |x|^2 partials
    float4 v0[2], v1[2];                             // two staging sets

    // ---- Prologue: chunks 0,1 loaded; STS 0; start chunk 2 ----
    #pragma unroll
    for (int p = 0; p < 2; p++) v0[p] = __ldg((const float4*)(xp + (size_t)(p * 8) * L_DIM));
    #pragma unroll
    for (int p = 0; p < 2; p++) v1[p] = __ldg((const float4*)(xp + (size_t)(KCHUNK + p * 8) * L_DIM));
    #pragma unroll
    for (int p = 0; p < 2; p++) {
        const float4 vv = v0[p];
        s0 = fmaf(vv.x, vv.x, s0); s1 = fmaf(vv.y, vv.y, s1);
        s2 = fmaf(vv.z, vv.z, s2); s3 = fmaf(vv.w, vv.w, s3);
        __nv_bfloat162 lo = __float22bfloat162_rn(make_float2(vv.x, vv.y));
        __nv_bfloat162 hi = __float22bfloat162_rn(make_float2(vv.z, vv.w));
        *(uint2*)(ap + (size_t)p * 8 * A_PITCH_B) = make_uint2(*(unsigned*)&lo, *(unsigned*)&hi);
    }
    #pragma unroll
    for (int p = 0; p < 2; p++) v0[p] = __ldg((const float4*)(xp + (size_t)(2 * KCHUNK + p * 8) * L_DIM));
    __syncthreads();

    // ---- Pipelined main loop: iter i -> STS(i+1), LDG(i+3), sync, mma(i) ----
    #pragma unroll
    for (int i = 0; i < NCHUNK; i++) {
        float4* vs = ((i + 1) & 1) ? v1 : v0;        // staging set for chunk i+1 / i+3
        if (i < NCHUNK - 1) {
            char* apb = ap + (size_t)((i + 1) % 3) * A_BUF_B;
            #pragma unroll
            for (int p = 0; p < 2; p++) {
                const float4 vv = vs[p];
                s0 = fmaf(vv.x, vv.x, s0); s1 = fmaf(vv.y, vv.y, s1);
                s2 = fmaf(vv.z, vv.z, s2); s3 = fmaf(vv.w, vv.w, s3);
                __nv_bfloat162 lo = __float22bfloat162_rn(make_float2(vv.x, vv.y));
                __nv_bfloat162 hi = __float22bfloat162_rn(make_float2(vv.z, vv.w));
                *(uint2*)(apb + (size_t)p * 8 * A_PITCH_B) = make_uint2(*(unsigned*)&lo, *(unsigned*)&hi);
            }
        }
        if (i < NCHUNK - 3) {
            const float* xn = xp + (size_t)((i + 3) * KCHUNK) * L_DIM;
            #pragma unroll
            for (int p = 0; p < 2; p++)
                vs[p] = __ldg((const float4*)(xn + (size_t)(p * 8) * L_DIM));
        }
        __syncthreads();

        // mma chunk i (one k16 step) from buffer i%3
        unsigned a0, a1, a2, a3;
        asm volatile(
            "ldmatrix.sync.aligned.m8n8.x4.trans.shared.b16 {%0,%1,%2,%3}, [%4];\n"
            : "=r"(a0), "=r"(a1), "=r"(a2), "=r"(a3)
            : "r"(aAddr + (i % 3) * A_BUF_B));
        #pragma unroll
        for (int nbp = 0; nbp < 4; nbp++) {
            const uint4 bb = wfs[(i * 4 + nbp) * 32 + lane];
            asm volatile(
                "mma.sync.aligned.m16n8k16.row.col.f32.bf16.bf16.f32 "
                "{%0,%1,%2,%3}, {%4,%5,%6,%7}, {%8,%9}, {%0,%1,%2,%3};\n"
                : "+f"(c[2*nbp][0]), "+f"(c[2*nbp][1]), "+f"(c[2*nbp][2]), "+f"(c[2*nbp][3])
                : "r"(a0), "r"(a1), "r"(a2), "r"(a3), "r"(bb.x), "r"(bb.y));
            asm volatile(
                "mma.sync.aligned.m16n8k16.row.col.f32.bf16.bf16.f32 "
                "{%0,%1,%2,%3}, {%4,%5,%6,%7}, {%8,%9}, {%0,%1,%2,%3};\n"
                : "+f"(c[2*nbp+1][0]), "+f"(c[2*nbp+1][1]), "+f"(c[2*nbp+1][2]), "+f"(c[2*nbp+1][3])
                : "r"(a0), "r"(a1), "r"(a2), "r"(a3), "r"(bb.z), "r"(bb.w));
        }
    }

    // ---- Finalize |x|^2: butterfly over ksl (lane bits 2..4) ----
    #pragma unroll
    for (int m = 4; m <= 16; m <<= 1) {
        s0 += __shfl_xor_sync(0xffffffffu, s0, m);
        s1 += __shfl_xor_sync(0xffffffffu, s1, m);
        s2 += __shfl_xor_sync(0xffffffffu, s2, m);
        s3 += __shfl_xor_sync(0xffffffffu, s3, m);
    }
    if (ksl == 0) {
        x2s[l0t]     = s0;
        x2s[l0t + 1] = s1;
        x2s[l0t + 2] = s2;
        x2s[l0t + 3] = s3;
    }
    __syncthreads();

    // ---- Epilogue ----
    const float ng  = -(*gptr);
    const float xa  = x2s[row];
    const float xb2 = x2s[row + 8];
    float* orow0 = out + (size_t)(m0 + row)     * O_DIM;
    float* orow1 = out + (size_t)(m0 + row + 8) * O_DIM;
    #pragma unroll
    for (int nb = 0; nb < 8; nb++) {
        const int o  = nb * 8 + t * 2;
        const float w20 = w2s[o], w21 = w2s[o + 1];
        const float bi0 = __ldg(bias + o), bi1 = __ldg(bias + o + 1);
        float2 r0, r1;
        r0.x = __expf(ng * (xa  + w20 - 2.f * c[nb][0])) + bi0;
        r0.y = __expf(ng * (xa  + w21 - 2.f * c[nb][1])) + bi1;
        r1.x = __expf(ng * (xb2 + w20 - 2.f * c[nb][2])) + bi0;
        r1.y = __expf(ng * (xb2 + w21 - 2.f * c[nb][3])) + bi1;
        *(float2*)(orow0 + o) = r0;
        *(float2*)(orow1 + o) = r1;
    }
}

extern "C" void kernel_launch(void* const* d_in, const int* in_sizes, int n_in,
                              void* d_out, int out_size)
{
    (void)in_sizes; (void)n_in; (void)out_size;
    const float* x     = (const float*)d_in[0];   // [8, 288, 16384]
    const float* w     = (const float*)d_in[1];   // [64,32,3,3] == flat [288][64]
    const float* bias  = (const float*)d_in[2];   // [64]
    const float* gamma = (const float*)d_in[3];   // scalar
    float* out = (float*)d_out;                   // [8, 16384, 64]

    cudaFuncSetAttribute(gauss_mma_kernel,
                         cudaFuncAttributeMaxDynamicSharedMemorySize, SMEM_TOT);

    gauss_init_kernel<<<(WF_UINT4 + 255) / 256, 256>>>(w);
    const int grid = (8 * L_DIM) / MT;            // 1024 CTAs
    gauss_mma_kernel<<<grid, TPB, SMEM_TOT>>>(x, bias, gamma, out);
}

// round 13
// speedup vs baseline: 1.2499x; 1.2499x over previous
#include <cuda_runtime.h>
#include <cuda_bf16.h>

// GaussianKernel via bf16 tensor-core GEMM, round 12:
//   out[b,l,o] = exp(-gamma*(|x|^2 + |w|^2 - 2 x.w)) + bias[o]
// GEMM [M=131072, N=64, K=288]. Change vs best (59.2us, R9): replace the
// LDG->reg->cvt->STS chain with cp.async (LDGSTS) into a 3-slot fp32 ring
// (depth-2 hardware pipeline, zero staging regs), plus a conflict-free
// smem->smem repack (LDS.128 -> cvt -> STS.64) into the proven swizzled
// bf16 A buffer (2 slots). mma/wf/epilogue machinery unchanged.

#define K_DIM   288
#define KCHUNK  16
#define NCHUNK  18
#define O_DIM   64
#define L_DIM   16384
#define TPB     256
#define MT      128
#define KSTEPS  18
#define A_PITCH_B 256                      // bytes per bf16 A row (128 bf16)
#define A_BUF_B  (KCHUNK * A_PITCH_B)      // 4096 per bf16 slot
#define XSLOT_B  (KCHUNK * MT * 4)         // 8192 per fp32 ring slot

#define WF_UINT4 (KSTEPS * 4 * 32)         // 2304 uint4 = 36864 B

__device__ uint4 g_wf[WF_UINT4];           // packed B fragments
__device__ float g_w2[O_DIM];

// smem layout (bytes)
#define SMEM_XR   0                        // fp32 ring: 3 x 8192 = 24576
#define SMEM_AB   (SMEM_XR + 3 * XSLOT_B)  // bf16 A: 2 x 4096 = 8192
#define SMEM_WF   (SMEM_AB + 2 * A_BUF_B)  // 36864
#define SMEM_X2R  (SMEM_WF + WF_UINT4 * 16)// [8][128] f32 = 4096
#define SMEM_W2   (SMEM_X2R + 8 * MT * 4)
#define SMEM_X2   (SMEM_W2 + O_DIM * 4)
#define SMEM_TOT  (SMEM_X2 + MT * 4)       // 74496 B -> 3 CTAs/SM

// ---------------------------------------------------------------------------
__global__ void gauss_init_kernel(const float* __restrict__ w)
{
    const int e = blockIdx.x * 256 + threadIdx.x;
    if (e < WF_UINT4) {
        const int lane = e & 31, nbp = (e >> 5) & 3, s = e >> 7;
        const int t = lane & 3, g = lane >> 2;
        const int k0 = s * 16 + t * 2;
        const int n0 = (2 * nbp) * 8 + g;
        const int n1 = n0 + 8;
        uint4 r;
        __nv_bfloat162 p;
        p = __float22bfloat162_rn(make_float2(w[(size_t)k0 * O_DIM + n0],
                                              w[(size_t)(k0 + 1) * O_DIM + n0]));
        r.x = *(unsigned*)&p;
        p = __float22bfloat162_rn(make_float2(w[(size_t)(k0 + 8) * O_DIM + n0],
                                              w[(size_t)(k0 + 9) * O_DIM + n0]));
        r.y = *(unsigned*)&p;
        p = __float22bfloat162_rn(make_float2(w[(size_t)k0 * O_DIM + n1],
                                              w[(size_t)(k0 + 1) * O_DIM + n1]));
        r.z = *(unsigned*)&p;
        p = __float22bfloat162_rn(make_float2(w[(size_t)(k0 + 8) * O_DIM + n1],
                                              w[(size_t)(k0 + 9) * O_DIM + n1]));
        r.w = *(unsigned*)&p;
        g_wf[e] = r;
    }
    if (blockIdx.x == 0 && threadIdx.x < O_DIM) {
        float s = 0.f;
        #pragma unroll 8
        for (int k = 0; k < K_DIM; k++) {
            const float v = w[(size_t)k * O_DIM + threadIdx.x];
            s = fmaf(v, v, s);
        }
        g_w2[threadIdx.x] = s;
    }
}

// ---------------------------------------------------------------------------
__device__ __forceinline__ void cp16(unsigned dst, const void* src)
{
    asm volatile("cp.async.ca.shared.global [%0], [%1], 16;\n"
                 :: "r"(dst), "l"(src));
}

__global__ void __launch_bounds__(TPB, 3)
gauss_mma_kernel(const float* __restrict__ x,
                 const float* __restrict__ bias,
                 const float* __restrict__ gptr,
                 float* __restrict__ out)
{
    extern __shared__ char smem[];
    char*     Xr  = smem + SMEM_XR;                  // fp32 ring, 3 slots
    char*     Ab  = smem + SMEM_AB;                  // bf16 A, 2 slots
    uint4*    wfs = (uint4*)(smem + SMEM_WF);        // [18*4][32]
    float*  x2red = (float*)(smem + SMEM_X2R);       // [8][128]
    float*    w2s = (float*)(smem + SMEM_W2);
    float*    x2s = (float*)(smem + SMEM_X2);

    const int tid  = threadIdx.x;
    const int lane = tid & 31;
    const int wp   = tid >> 5;                       // 0..7

    const int m0 = blockIdx.x * MT;                  // 1024 CTAs
    const int b  = m0 >> 14;
    const int lb = m0 & (L_DIM - 1);
    const float* xb = x + (size_t)b * K_DIM * L_DIM + lb + lane * 4;

    // cp.async addressing: thread covers rows kc = 8r+wp (r=0,1), 16B at l=lane*4.
    const unsigned xrBase = (unsigned)__cvta_generic_to_shared(Xr)
                          + (unsigned)(wp * 512 + lane * 16);

    // ---- Kick off chunks 0 and 1 ----
    #pragma unroll
    for (int c = 0; c < 2; c++) {
        #pragma unroll
        for (int r = 0; r < 2; r++)
            cp16(xrBase + c * XSLOT_B + r * 4096,
                 xb + (size_t)(c * KCHUNK + 8 * r + wp) * L_DIM);
        asm volatile("cp.async.commit_group;\n");
    }

    // ---- Copy packed w fragments + w2 to smem (flies during cp.async) ----
    #pragma unroll
    for (int i = 0; i < WF_UINT4 / TPB; i++)         // 9
        wfs[tid + TPB * i] = g_wf[tid + TPB * i];
    if (tid < O_DIM) w2s[tid] = g_w2[tid];

    // repack source/dest addressing
    const char* xrRead = Xr + wp * 512 + lane * 16;
    // bf16 write: row kc, 8B at swizzled offset (lane*8)^(wp*16)  (kc&7 == wp)
    char* abW = Ab + ((lane * 8) ^ (wp * 16));

    // ldmatrix source address within bf16 slot 0 (proven formulas)
    unsigned aAddr;
    {
        const int kr = (lane & 7) | ((lane >> 4) << 3);
        const int cb = 2 * wp + ((lane >> 3) & 1);
        const char* p = Ab + (size_t)kr * A_PITCH_B + ((cb ^ (lane & 7)) * 16);
        aAddr = (unsigned)__cvta_generic_to_shared(p);
    }

    const int g = lane >> 2;
    const int t = lane & 3;
    const int row = wp * 16 + g;

    float c[8][4];
    #pragma unroll
    for (int nb = 0; nb < 8; nb++)
        #pragma unroll
        for (int q = 0; q < 4; q++) c[nb][q] = 0.f;

    float s0 = 0.f, s1 = 0.f, s2 = 0.f, s3 = 0.f;    // |x|^2 partials (l = lane*4+j)

    // ---- Pipelined main loop ----
    // iter i: issue cp.async chunk i+2; commit; wait chunk i; repack i; sync; mma i.
    #pragma unroll 3
    for (int i = 0; i < NCHUNK; i++) {
        if (i + 2 < NCHUNK) {
            const int cnx = i + 2;
            #pragma unroll
            for (int r = 0; r < 2; r++)
                cp16(xrBase + (cnx % 3) * XSLOT_B + r * 4096,
                     xb + (size_t)(cnx * KCHUNK + 8 * r + wp) * L_DIM);
        }
        asm volatile("cp.async.commit_group;\n");     // uniform group per iter
        asm volatile("cp.async.wait_group 2;\n");     // chunk i arrived (own warp)

        // repack chunk i: fp32 slot i%3 -> bf16 slot i&1, + |x|^2
        {
            const char* src = xrRead + (i % 3) * XSLOT_B;
            char* dst = abW + (i & 1) * A_BUF_B;
            #pragma unroll
            for (int r = 0; r < 2; r++) {
                const float4 v = *(const float4*)(src + r * 4096);
                s0 = fmaf(v.x, v.x, s0); s1 = fmaf(v.y, v.y, s1);
                s2 = fmaf(v.z, v.z, s2); s3 = fmaf(v.w, v.w, s3);
                __nv_bfloat162 lo = __float22bfloat162_rn(make_float2(v.x, v.y));
                __nv_bfloat162 hi = __float22bfloat162_rn(make_float2(v.z, v.w));
                *(uint2*)(dst + (8 * r + wp) * A_PITCH_B) =
                    make_uint2(*(unsigned*)&lo, *(unsigned*)&hi);
            }
        }
        __syncthreads();

        // mma chunk i (one k16 step) from bf16 slot i&1
        unsigned a0, a1, a2, a3;
        asm volatile(
            "ldmatrix.sync.aligned.m8n8.x4.trans.shared.b16 {%0,%1,%2,%3}, [%4];\n"
            : "=r"(a0), "=r"(a1), "=r"(a2), "=r"(a3)
            : "r"(aAddr + (i & 1) * A_BUF_B));
        #pragma unroll
        for (int nbp = 0; nbp < 4; nbp++) {
            const uint4 bb = wfs[(i * 4 + nbp) * 32 + lane];
            asm volatile(
                "mma.sync.aligned.m16n8k16.row.col.f32.bf16.bf16.f32 "
                "{%0,%1,%2,%3}, {%4,%5,%6,%7}, {%8,%9}, {%0,%1,%2,%3};\n"
                : "+f"(c[2*nbp][0]), "+f"(c[2*nbp][1]), "+f"(c[2*nbp][2]), "+f"(c[2*nbp][3])
                : "r"(a0), "r"(a1), "r"(a2), "r"(a3), "r"(bb.x), "r"(bb.y));
            asm volatile(
                "mma.sync.aligned.m16n8k16.row.col.f32.bf16.bf16.f32 "
                "{%0,%1,%2,%3}, {%4,%5,%6,%7}, {%8,%9}, {%0,%1,%2,%3};\n"
                : "+f"(c[2*nbp+1][0]), "+f"(c[2*nbp+1][1]), "+f"(c[2*nbp+1][2]), "+f"(c[2*nbp+1][3])
                : "r"(a0), "r"(a1), "r"(a2), "r"(a3), "r"(bb.z), "r"(bb.w));
        }
    }

    // ---- |x|^2 reduction over warps ----
    float* xr = x2red + wp * MT + lane * 4;
    xr[0] = s0; xr[1] = s1; xr[2] = s2; xr[3] = s3;
    __syncthreads();
    if (tid < MT) {
        float s = 0.f;
        #pragma unroll
        for (int k = 0; k < 8; k++) s += x2red[k * MT + tid];
        x2s[tid] = s;
    }
    __syncthreads();

    // ---- Epilogue ----
    const float ng  = -(*gptr);
    const float xa  = x2s[row];
    const float xb2 = x2s[row + 8];
    float* orow0 = out + (size_t)(m0 + row)     * O_DIM;
    float* orow1 = out + (size_t)(m0 + row + 8) * O_DIM;
    #pragma unroll
    for (int nb = 0; nb < 8; nb++) {
        const int o  = nb * 8 + t * 2;
        const float w20 = w2s[o], w21 = w2s[o + 1];
        const float bi0 = __ldg(bias + o), bi1 = __ldg(bias + o + 1);
        float2 r0, r1;
        r0.x = __expf(ng * (xa  + w20 - 2.f * c[nb][0])) + bi0;
        r0.y = __expf(ng * (xa  + w21 - 2.f * c[nb][1])) + bi1;
        r1.x = __expf(ng * (xb2 + w20 - 2.f * c[nb][2])) + bi0;
        r1.y = __expf(ng * (xb2 + w21 - 2.f * c[nb][3])) + bi1;
        *(float2*)(orow0 + o) = r0;
        *(float2*)(orow1 + o) = r1;
    }
}

extern "C" void kernel_launch(void* const* d_in, const int* in_sizes, int n_in,
                              void* d_out, int out_size)
{
    (void)in_sizes; (void)n_in; (void)out_size;
    const float* x     = (const float*)d_in[0];   // [8, 288, 16384]
    const float* w     = (const float*)d_in[1];   // [64,32,3,3] == flat [288][64]
    const float* bias  = (const float*)d_in[2];   // [64]
    const float* gamma = (const float*)d_in[3];   // scalar
    float* out = (float*)d_out;                   // [8, 16384, 64]

    cudaFuncSetAttribute(gauss_mma_kernel,
                         cudaFuncAttributeMaxDynamicSharedMemorySize, SMEM_TOT);

    gauss_init_kernel<<<(WF_UINT4 + 255) / 256, 256>>>(w);
    const int grid = (8 * L_DIM) / MT;            // 1024 CTAs
    gauss_mma_kernel<<<grid, TPB, SMEM_TOT>>>(x, bias, gamma, out);
}